// round 12
// baseline (speedup 1.0000x reference)
#include <cuda_runtime.h>
#include <cuda_bf16.h>
#include <math.h>
#include <stdint.h>

#define BATCH 8
#define NPATCH 196
#define LEN_KEEP 147
#define SEQL 148
#define DM 768
#define DI 1536
#define DSTATE 16
#define DTR 48
#define XDBLN 80
#define NLAYERS 12
#define MROWS (BATCH*SEQL)   // 1184

// ---------------- scratch buffers (device globals; no allocation) ----------------
__device__ float g_patches[MROWS*DM];
__device__ int   g_rowpatch[MROWS];
__device__ float g_h[MROWS*DM];
__device__ float g_ln[MROWS*DM];
__device__ float g_xz[MROWS*2*DI];
__device__ float g_xc[MROWS*DI];
__device__ float g_xdbl[MROWS*XDBLN];
__device__ float g_y[MROWS*DI];

// ================= low-level helpers =================
__device__ __forceinline__ uint32_t smem_u32(const void* p) {
    uint32_t a;
    asm("{ .reg .u64 t; cvta.to.shared.u64 t, %1; cvt.u32.u64 %0, t; }" : "=r"(a) : "l"(p));
    return a;
}
__device__ __forceinline__ void ldsm4(uint32_t* r, uint32_t addr) {
    asm volatile("ldmatrix.sync.aligned.m8n8.x4.shared.b16 {%0,%1,%2,%3}, [%4];"
                 : "=r"(r[0]), "=r"(r[1]), "=r"(r[2]), "=r"(r[3]) : "r"(addr));
}
__device__ __forceinline__ void mma16816(float* d, const uint32_t* a, const uint32_t* b) {
    asm volatile("mma.sync.aligned.m16n8k16.row.col.f32.bf16.bf16.f32 "
                 "{%0,%1,%2,%3}, {%4,%5,%6,%7}, {%8,%9}, {%0,%1,%2,%3};"
                 : "+f"(d[0]), "+f"(d[1]), "+f"(d[2]), "+f"(d[3])
                 : "r"(a[0]), "r"(a[1]), "r"(a[2]), "r"(a[3]), "r"(b[0]), "r"(b[1]));
}

// ======== bf16x3 tensor GEMM: C[M,N] (+)= A[M,lda] * W[N,ldb]^T over K-slice ======
// 128x128 CTA tile, 8 warps (2x4), 64x32 warp tile, 16-float K stages (hi|lo bf16).
// EPI: 0 = plain store, 1 = atomicAdd accumulate (for split-K residual add)
template<int EPI>
__global__ __launch_bounds__(256, 2)
void mma_bf16x3(const float* __restrict__ A, const float* __restrict__ W,
                float* __restrict__ C, int M, int N, int lda, int ldb, int Klen) {
    constexpr int PITCH = 40;                 // bf16 elems per row: [hi 16 | lo 16 | pad 8]
    constexpr int ROWB  = PITCH * 2;          // 80 bytes
    constexpr int STAGEB = 128 * ROWB;        // bytes per stage buffer
    __shared__ __align__(16) __nv_bfloat16 As[2][128][PITCH];
    __shared__ __align__(16) __nv_bfloat16 Bs[2][128][PITCH];

    const int tid  = threadIdx.x;
    const int lane = tid & 31;
    const int wid  = tid >> 5;
    const int wm   = wid & 1;                 // 2 warps along M
    const int wn   = wid >> 1;                // 4 warps along N
    const int m0   = blockIdx.x * 128;
    const int n0   = blockIdx.y * 128;
    const int koff = blockIdx.z * Klen;

    float acc[4][4][4];
    #pragma unroll
    for (int i = 0; i < 4; i++)
        #pragma unroll
        for (int j = 0; j < 4; j++)
            #pragma unroll
            for (int q = 0; q < 4; q++) acc[i][j][q] = 0.0f;

    // conflict-free staging mapping
    const int lrow = (tid & 7) | (((tid >> 4) & 1) << 3) | ((tid >> 5) << 4);
    const int lkc  = ((tid >> 3) & 1) * 8;    // k-chunk: floats 0-7 or 8-15
    const int gmA  = m0 + lrow;
    const bool mok = (gmA < M);
    const float* aPtr = A + (size_t)gmA * lda + koff + lkc;
    const float* bPtr = W + (size_t)(n0 + lrow) * ldb + koff + lkc;

    const uint32_t aAddr = smem_u32(&As[0][wm*64 + (lane & 15)][0]) + ((lane >> 4) * 16);
    const uint32_t bAddr = smem_u32(&Bs[0][wn*32 + ((lane >> 4) << 3) + (lane & 7)][0])
                         + (((lane >> 3) & 1) * 16);

    const int KT = Klen / 16;

    // split-store: 8 floats -> hi bf16 16B chunk + lo bf16 16B chunk
    auto split_sts = [&](__nv_bfloat16 (*S)[PITCH], float4 v0, float4 v1) {
        float f[8] = {v0.x, v0.y, v0.z, v0.w, v1.x, v1.y, v1.z, v1.w};
        uint4 hi4, lo4;
        uint32_t* hp = (uint32_t*)&hi4;
        uint32_t* lp = (uint32_t*)&lo4;
        #pragma unroll
        for (int q = 0; q < 4; q++) {
            float x = f[2*q], y = f[2*q+1];
            __nv_bfloat162 h2 = __floats2bfloat162_rn(x, y);
            float2 hf = __bfloat1622float2(h2);
            __nv_bfloat162 l2 = __floats2bfloat162_rn(x - hf.x, y - hf.y);
            hp[q] = *(uint32_t*)&h2;
            lp[q] = *(uint32_t*)&l2;
        }
        *(uint4*)&S[lrow][lkc]      = hi4;
        *(uint4*)&S[lrow][16 + lkc] = lo4;
    };

    // ---- stage 0 ----
    {
        float4 va0 = make_float4(0,0,0,0), va1 = va0;
        if (mok) { va0 = *(const float4*)aPtr; va1 = *(const float4*)(aPtr + 4); }
        float4 vb0 = *(const float4*)bPtr, vb1 = *(const float4*)(bPtr + 4);
        split_sts(As[0], va0, va1);
        split_sts(Bs[0], vb0, vb1);
    }
    __syncthreads();

    int s = 0;
    for (int kt = 0; kt < KT; kt++) {
        float4 va0, va1, vb0, vb1;
        if (kt + 1 < KT) {
            int k0 = (kt + 1) * 16;
            va0 = make_float4(0,0,0,0); va1 = va0;
            if (mok) { va0 = *(const float4*)(aPtr + k0); va1 = *(const float4*)(aPtr + k0 + 4); }
            vb0 = *(const float4*)(bPtr + k0); vb1 = *(const float4*)(bPtr + k0 + 4);
        }

        // ---- compute stage s: acc += Ah*Bh + Ah*Bl + Al*Bh ----
        {
            const uint32_t aS = aAddr + s * STAGEB;
            const uint32_t bS = bAddr + s * STAGEB;
            uint32_t Af[4][4], Bh[4][2], Bl[4][2], t[4];

            #pragma unroll
            for (int mf = 0; mf < 4; mf++) ldsm4(Af[mf], aS + mf * 16 * ROWB);     // A hi
            ldsm4(t, bS);                 Bh[0][0]=t[0]; Bh[0][1]=t[1]; Bh[1][0]=t[2]; Bh[1][1]=t[3];
            ldsm4(t, bS + 16 * ROWB);     Bh[2][0]=t[0]; Bh[2][1]=t[1]; Bh[3][0]=t[2]; Bh[3][1]=t[3];
            #pragma unroll
            for (int mf = 0; mf < 4; mf++)
                #pragma unroll
                for (int nf = 0; nf < 4; nf++) mma16816(acc[mf][nf], Af[mf], Bh[nf]);

            ldsm4(t, bS + 32);            Bl[0][0]=t[0]; Bl[0][1]=t[1]; Bl[1][0]=t[2]; Bl[1][1]=t[3];
            ldsm4(t, bS + 16*ROWB + 32);  Bl[2][0]=t[0]; Bl[2][1]=t[1]; Bl[3][0]=t[2]; Bl[3][1]=t[3];
            #pragma unroll
            for (int mf = 0; mf < 4; mf++)
                #pragma unroll
                for (int nf = 0; nf < 4; nf++) mma16816(acc[mf][nf], Af[mf], Bl[nf]);

            #pragma unroll
            for (int mf = 0; mf < 4; mf++) ldsm4(Af[mf], aS + mf * 16 * ROWB + 32); // A lo
            #pragma unroll
            for (int mf = 0; mf < 4; mf++)
                #pragma unroll
                for (int nf = 0; nf < 4; nf++) mma16816(acc[mf][nf], Af[mf], Bh[nf]);
        }

        if (kt + 1 < KT) {
            int sn = s ^ 1;
            split_sts(As[sn], va0, va1);
            split_sts(Bs[sn], vb0, vb1);
            __syncthreads();
            s = sn;
        }
    }

    // ---- epilogue ----
    #pragma unroll
    for (int mf = 0; mf < 4; mf++) {
        int r0 = m0 + wm*64 + mf*16 + (lane >> 2);
        #pragma unroll
        for (int nf = 0; nf < 4; nf++) {
            int c = n0 + wn*32 + nf*8 + (lane & 3)*2;
            if (EPI == 0) {
                if (r0 < M)     *(float2*)&C[(size_t)r0 * N + c]     = make_float2(acc[mf][nf][0], acc[mf][nf][1]);
                if (r0 + 8 < M) *(float2*)&C[(size_t)(r0+8) * N + c] = make_float2(acc[mf][nf][2], acc[mf][nf][3]);
            } else {
                if (r0 < M) {
                    atomicAdd(&C[(size_t)r0 * N + c],     acc[mf][nf][0]);
                    atomicAdd(&C[(size_t)r0 * N + c + 1], acc[mf][nf][1]);
                }
                if (r0 + 8 < M) {
                    atomicAdd(&C[(size_t)(r0+8) * N + c],     acc[mf][nf][2]);
                    atomicAdd(&C[(size_t)(r0+8) * N + c + 1], acc[mf][nf][3]);
                }
            }
        }
    }
}

// ---------------- packed f32x2 helpers (FFMA2 kernels) ----------------------------
__device__ __forceinline__ void ffma2(unsigned long long& acc,
                                      unsigned long long a, unsigned long long b) {
    asm("fma.rn.f32x2 %0, %1, %2, %0;" : "+l"(acc) : "l"(a), "l"(b));
}
__device__ __forceinline__ unsigned long long pack2(float x, float y) {
    unsigned long long r;
    asm("mov.b64 %0, {%1, %2};" : "=l"(r) : "f"(x), "f"(y));
    return r;
}
__device__ __forceinline__ float2 unpack2(unsigned long long v) {
    float2 f;
    asm("mov.b64 {%0, %1}, %2;" : "=f"(f.x), "=f"(f.y) : "l"(v));
    return f;
}

// -------- fused masking + gather: every block recomputes ranks from noise --------
__global__ void maskgather_kernel(const float* __restrict__ noise,
                                  const float* __restrict__ pix,
                                  float* __restrict__ out_mask,
                                  float* __restrict__ out_ids) {
    __shared__ float s[NPATCH];
    __shared__ int p_sel;
    int m = blockIdx.x;
    int t = m % SEQL, b = m / SEQL;
    int tid = threadIdx.x;
    if (tid < NPATCH) s[tid] = noise[b*NPATCH + tid];
    __syncthreads();
    int rank = -1;
    if (tid < NPATCH) {
        float v = s[tid];
        rank = 0;
        #pragma unroll 4
        for (int j = 0; j < NPATCH; j++) {
            float u = s[j];
            rank += (u < v) || (u == v && j < tid);
        }
    }
    if (t == 0) {
        if (tid < NPATCH) {
            out_mask[b*NPATCH + tid] = (rank >= LEN_KEEP) ? 1.0f : 0.0f;
            out_ids [b*NPATCH + tid] = (float)rank;
        }
        if (tid == 0) g_rowpatch[m] = -1;
        for (int k = tid; k < DM; k += blockDim.x) g_patches[m*DM + k] = 0.0f;
        return;
    }
    if (rank == t - 1) p_sel = tid;      // exactly one thread matches
    __syncthreads();
    int p = p_sel;
    if (tid == 0) g_rowpatch[m] = p;
    int pi = p / 14, pj = p % 14;
    for (int k = tid; k < DM; k += blockDim.x) {
        int c = k >> 8, rem = k & 255, r = rem >> 4, cc = rem & 15;
        g_patches[m*DM + k] =
            pix[((size_t)(b*3 + c)*224 + pi*16 + r)*224 + pj*16 + cc];
    }
}

// =============== FFMA2 SGEMM (patch-embed) =========================================
// EPI: 1 patch-embed
template<int EPI>
__global__ __launch_bounds__(256)
void sgemm3(const float* __restrict__ A, const float* __restrict__ W,
            float* __restrict__ C, int M, int N, int K, int lda, int Klen,
            const float* __restrict__ ep0, const float* __restrict__ ep1,
            const float* __restrict__ ep2, const int* __restrict__ rowinfo) {
    constexpr int BM = 64, BN = 64, BK = 16;
    constexpr int PA = 132;
    constexpr int PB = 68;
    __shared__ __align__(16) float As2[2][BK][PA];
    __shared__ __align__(16) float Bs [2][BK][PB];
    const int tid = threadIdx.x;
    const int m0 = blockIdx.x * BM;
    const int n0 = blockIdx.y * BN;
    const int koff = blockIdx.z * Klen;
    const int tx = tid & 15;
    const int ty = tid >> 4;
    unsigned long long acc[4][2];
    #pragma unroll
    for (int i = 0; i < 4; i++) { acc[i][0] = 0ull; acc[i][1] = 0ull; }
    const int KT = Klen / BK;
    const int li = tid >> 4, lj = tid & 15;
    #pragma unroll
    for (int r = 0; r < 4; r++) {
        int i = li + r*16;
        int gm = m0 + i;
        float va = (gm < M) ? A[(size_t)gm * lda + koff + lj] : 0.0f;
        *(unsigned long long*)&As2[0][lj][2*i] = pack2(va, va);
        Bs[0][lj][i] = W[(size_t)(n0 + i) * K + koff + lj];
    }
    __syncthreads();
    int s = 0;
    for (int kt = 0; kt < KT; kt++) {
        float ra[4], rb[4];
        if (kt + 1 < KT) {
            int k0 = koff + (kt + 1) * BK;
            #pragma unroll
            for (int r = 0; r < 4; r++) {
                int i = li + r*16;
                int gm = m0 + i;
                ra[r] = (gm < M) ? A[(size_t)gm * lda + k0 + lj] : 0.0f;
                rb[r] = W[(size_t)(n0 + i) * K + k0 + lj];
            }
        }
        #pragma unroll
        for (int kk = 0; kk < BK; kk++) {
            ulonglong2 a01 = *(const ulonglong2*)&As2[s][kk][ty*8];
            ulonglong2 a23 = *(const ulonglong2*)&As2[s][kk][ty*8 + 4];
            ulonglong2 bq  = *(const ulonglong2*)&Bs [s][kk][tx*4];
            ffma2(acc[0][0], a01.x, bq.x); ffma2(acc[0][1], a01.x, bq.y);
            ffma2(acc[1][0], a01.y, bq.x); ffma2(acc[1][1], a01.y, bq.y);
            ffma2(acc[2][0], a23.x, bq.x); ffma2(acc[2][1], a23.x, bq.y);
            ffma2(acc[3][0], a23.y, bq.x); ffma2(acc[3][1], a23.y, bq.y);
        }
        if (kt + 1 < KT) {
            int sn = s ^ 1;
            #pragma unroll
            for (int r = 0; r < 4; r++) {
                int i = li + r*16;
                *(unsigned long long*)&As2[sn][lj][2*i] = pack2(ra[r], ra[r]);
                Bs[sn][lj][i] = rb[r];
            }
            __syncthreads();
            s = sn;
        }
    }
    #pragma unroll
    for (int i = 0; i < 4; i++) {
        int m = m0 + ty*4 + i;
        if (m >= M) continue;
        int rp = 0;
        if (EPI == 1) rp = rowinfo[m];
        #pragma unroll
        for (int j = 0; j < 2; j++) {
            float2 v2 = unpack2(acc[i][j]);
            int n = n0 + tx*4 + j*2;
            float vv[2] = {v2.x, v2.y};
            #pragma unroll
            for (int q = 0; q < 2; q++) {
                int nn = n + q;
                float v = vv[q];
                if (rp < 0) v = ep1[nn] + ep2[nn];
                else        v = v + ep0[nn] + ep2[(size_t)(1+rp)*DM + nn];
                C[(size_t)m * N + nn] = v;
            }
        }
    }
}

// ---------------- small SGEMM for x_dbl (N=80), split-K with atomicAdd ------------
template<int BM, int BN, int BK, int TM, int TN>
__global__ __launch_bounds__(256)
void sgemm_small(const float* __restrict__ A, const float* __restrict__ W,
                 float* __restrict__ C, int M, int N, int K, int lda, int Klen) {
    __shared__ float As[BK][BM + 4];
    __shared__ float Bs[BK][BN + 4];
    const int tid = threadIdx.x;
    const int m0 = blockIdx.x * BM;
    const int n0 = blockIdx.y * BN;
    const int koff = blockIdx.z * Klen;
    constexpr int CT = BN / TN;
    const int tx = tid % CT;
    const int ty = tid / CT;
    float acc[TM][TN];
    #pragma unroll
    for (int i = 0; i < TM; i++)
        #pragma unroll
        for (int j = 0; j < TN; j++) acc[i][j] = 0.0f;
    constexpr int AREP = (BM * BK) / 256;
    constexpr int BREP = (BN * BK + 255) / 256;
    for (int k0 = koff; k0 < koff + Klen; k0 += BK) {
        #pragma unroll
        for (int r = 0; r < AREP; r++) {
            int idx = tid + r * 256;
            int i = idx / BK, j = idx % BK;
            int gm = m0 + i;
            As[j][i] = (gm < M) ? A[(size_t)gm * lda + k0 + j] : 0.0f;
        }
        #pragma unroll
        for (int r = 0; r < BREP; r++) {
            int idx = tid + r * 256;
            if (idx < BN * BK) {
                int i = idx / BK, j = idx % BK;
                Bs[j][i] = W[(size_t)(n0 + i) * K + k0 + j];
            }
        }
        __syncthreads();
        #pragma unroll
        for (int kk = 0; kk < BK; kk++) {
            float a[TM], bb[TN];
            #pragma unroll
            for (int i = 0; i < TM; i++) a[i] = As[kk][ty*TM + i];
            #pragma unroll
            for (int j = 0; j < TN; j++) bb[j] = Bs[kk][tx*TN + j];
            #pragma unroll
            for (int i = 0; i < TM; i++)
                #pragma unroll
                for (int j = 0; j < TN; j++)
                    acc[i][j] = fmaf(a[i], bb[j], acc[i][j]);
        }
        __syncthreads();
    }
    #pragma unroll
    for (int i = 0; i < TM; i++) {
        int m = m0 + ty*TM + i;
        if (m >= M) continue;
        #pragma unroll
        for (int j = 0; j < TN; j++) {
            int n = n0 + tx*TN + j;
            atomicAdd(&C[(size_t)m * N + n], acc[i][j]);
        }
    }
}

// ---------------- depthwise causal conv1d (k=4) + SiLU; also zeroes xdbl row -----
__global__ void conv_silu_kernel(const float* __restrict__ cw,
                                 const float* __restrict__ cb) {
    int m = blockIdx.x;
    int t = m % SEQL, b = m / SEQL;
    if (threadIdx.x < XDBLN) g_xdbl[(size_t)m*XDBLN + threadIdx.x] = 0.0f;
    for (int d = threadIdx.x; d < DI; d += blockDim.x) {
        float w0 = cw[d*4+0], w1 = cw[d*4+1], w2 = cw[d*4+2], w3 = cw[d*4+3];
        float s = cb[d];
        const float* base = g_xz + (size_t)(b*SEQL) * (2*DI) + d;
        if (t >= 3) s = fmaf(w0, base[(size_t)(t-3)*(2*DI)], s);
        if (t >= 2) s = fmaf(w1, base[(size_t)(t-2)*(2*DI)], s);
        if (t >= 1) s = fmaf(w2, base[(size_t)(t-1)*(2*DI)], s);
        s = fmaf(w3, base[(size_t)t*(2*DI)], s);
        float sig = 1.0f / (1.0f + __expf(-s));
        g_xc[(size_t)m*DI + d] = s * sig;
    }
}

// ---------------- layernorm (row per block, 256 threads, DM=768) -----------------
__device__ __forceinline__ float block_reduce_sum_256(float v, float* sh, float* bc) {
    #pragma unroll
    for (int o = 16; o > 0; o >>= 1) v += __shfl_xor_sync(0xffffffffu, v, o);
    int w = threadIdx.x >> 5;
    if ((threadIdx.x & 31) == 0) sh[w] = v;
    __syncthreads();
    if (threadIdx.x == 0) {
        float s = 0.0f;
        #pragma unroll
        for (int i = 0; i < 8; i++) s += sh[i];
        *bc = s;
    }
    __syncthreads();
    return *bc;
}

__global__ void ln_kernel(const float* __restrict__ x, const float* __restrict__ w,
                          const float* __restrict__ bias, float* __restrict__ out) {
    __shared__ float sh[8];
    __shared__ float bc;
    int m = blockIdx.x, tid = threadIdx.x;
    const float* xr = x + (size_t)m * DM;
    float v0 = xr[tid], v1 = xr[tid + 256], v2 = xr[tid + 512];
    float mean = block_reduce_sum_256(v0 + v1 + v2, sh, &bc) * (1.0f / DM);
    float d0 = v0 - mean, d1 = v1 - mean, d2 = v2 - mean;
    __syncthreads();
    float var = block_reduce_sum_256(d0*d0 + d1*d1 + d2*d2, sh, &bc) * (1.0f / DM);
    float inv = rsqrtf(var + 1e-12f);
    float* o = out + (size_t)m * DM;
    o[tid]       = d0 * inv * w[tid]       + bias[tid];
    o[tid + 256] = d1 * inv * w[tid + 256] + bias[tid + 256];
    o[tid + 512] = d2 * inv * w[tid + 512] + bias[tid + 512];
}

// ---------------- selective scan with fused dt projection -------------------------
// 16 lanes per channel; lane n computes 3 of the K=48 dt dot-product terms,
// butterfly-reduces, softplus; then the usual state update + output reduction.
// 128-thread blocks (4 warps, 8 channels) for better SM spread: 1536 blocks.
__global__ void scan_kernel(const float* __restrict__ A_log_l,
                            const float* __restrict__ Dp_l,
                            const float* __restrict__ Wd_l,
                            const float* __restrict__ db_l) {
    int lane = threadIdx.x & 31;
    int warp = threadIdx.x >> 5;
    int widx = blockIdx.x * 4 + warp;
    int ch = widx * 2 + (lane >> 4);       // 2 channels per warp
    int b = ch / DI, d = ch % DI;
    int n = lane & 15;
    float Av = -__expf(A_log_l[d*DSTATE + n]);
    float Dv = Dp_l[d];
    float wd0 = Wd_l[d*DTR + 3*n + 0];
    float wd1 = Wd_l[d*DTR + 3*n + 1];
    float wd2 = Wd_l[d*DTR + 3*n + 2];
    float dbias = db_l[d];
    float h = 0.0f;
    int base = b * SEQL;
    for (int t = 0; t < SEQL; t++) {
        int m = base + t;
        const float* xr = g_xdbl + (size_t)m*XDBLN;
        // fused dt projection: dot(xdbl[m, :48], W_dt[d, :48]) across 16 lanes
        float dtp = xr[3*n]*wd0 + xr[3*n+1]*wd1 + xr[3*n+2]*wd2;
        dtp += __shfl_xor_sync(0xffffffffu, dtp, 8);
        dtp += __shfl_xor_sync(0xffffffffu, dtp, 4);
        dtp += __shfl_xor_sync(0xffffffffu, dtp, 2);
        dtp += __shfl_xor_sync(0xffffffffu, dtp, 1);
        float xdt = dtp + dbias;
        float dt = (xdt > 20.0f) ? xdt : log1pf(__expf(xdt));
        float xc = g_xc[(size_t)m*DI + d];
        float Bn = xr[DTR + n];
        float Cn = xr[DTR + DSTATE + n];
        float dA = __expf(dt * Av);
        h = fmaf(dA, h, (dt * xc) * Bn);
        float p = h * Cn;
        p += __shfl_xor_sync(0xffffffffu, p, 8);
        p += __shfl_xor_sync(0xffffffffu, p, 4);
        p += __shfl_xor_sync(0xffffffffu, p, 2);
        p += __shfl_xor_sync(0xffffffffu, p, 1);
        if (n == 0) {
            float z = g_xz[(size_t)m*(2*DI) + DI + d];
            float y = (p + xc * Dv) * (z / (1.0f + __expf(-z)));
            g_y[(size_t)m*DI + d] = y;
        }
    }
}

// ---------------- host launcher ---------------------------------------------------
extern "C" void kernel_launch(void* const* d_in, const int* in_sizes, int n_in,
                              void* d_out, int out_size) {
    const float* pixel     = (const float*)d_in[0];
    const float* noise     = (const float*)d_in[1];
    const float* conv_w    = (const float*)d_in[2];
    const float* conv_b    = (const float*)d_in[3];
    const float* cls_token = (const float*)d_in[4];
    const float* pos_embed = (const float*)d_in[5];
    const float* ln_w      = (const float*)d_in[6];
    const float* ln_b      = (const float*)d_in[7];
    const float* W_in      = (const float*)d_in[8];
    const float* conv1d_w  = (const float*)d_in[9];
    const float* conv1d_b  = (const float*)d_in[10];
    const float* W_x       = (const float*)d_in[11];
    const float* W_dt      = (const float*)d_in[12];
    const float* dt_bias   = (const float*)d_in[13];
    const float* A_log     = (const float*)d_in[14];
    const float* Dp        = (const float*)d_in[15];
    const float* W_out     = (const float*)d_in[16];
    const float* lnf_w     = (const float*)d_in[17];
    const float* lnf_b     = (const float*)d_in[18];

    float* out      = (float*)d_out;
    float* out_h    = out;                       // (8,148,768)
    float* out_mask = out + (size_t)MROWS*DM;    // (8,196)
    float* out_ids  = out_mask + BATCH*NPATCH;   // (8,196) as float

    float *p_patches, *p_h, *p_ln, *p_xz, *p_xc, *p_xdbl, *p_y;
    int *p_rowpatch;
    cudaGetSymbolAddress((void**)&p_patches, g_patches);
    cudaGetSymbolAddress((void**)&p_h,       g_h);
    cudaGetSymbolAddress((void**)&p_ln,      g_ln);
    cudaGetSymbolAddress((void**)&p_xz,      g_xz);
    cudaGetSymbolAddress((void**)&p_xc,      g_xc);
    cudaGetSymbolAddress((void**)&p_xdbl,    g_xdbl);
    cudaGetSymbolAddress((void**)&p_y,       g_y);
    cudaGetSymbolAddress((void**)&p_rowpatch, g_rowpatch);

    const int MB64  = (MROWS + 63) / 64;     // 19
    const int MB128 = (MROWS + 127) / 128;   // 10

    // fused masking + patch gather (launch #1), then patch-embed GEMM (#2)
    maskgather_kernel<<<MROWS, 256>>>(noise, pixel, out_mask, out_ids);
    sgemm3<1><<<dim3(MB64, DM/64, 1), 256>>>(p_patches, conv_w, p_h,
        MROWS, DM, DM, DM, DM, conv_b, cls_token, pos_embed, p_rowpatch);

    for (int l = 0; l < NLAYERS; l++) {
        const float* Wi  = W_in     + (size_t)l * (2*DI) * DM;
        const float* cw  = conv1d_w + (size_t)l * DI * 4;
        const float* cb  = conv1d_b + (size_t)l * DI;
        const float* Wx  = W_x      + (size_t)l * XDBLN * DI;
        const float* Wd  = W_dt     + (size_t)l * DI * DTR;
        const float* db  = dt_bias  + (size_t)l * DI;
        const float* Al  = A_log    + (size_t)l * DI * DSTATE;
        const float* Dl  = Dp       + (size_t)l * DI;
        const float* Wo  = W_out    + (size_t)l * DM * DI;

        // layernorm (#3 in layer 0)
        ln_kernel<<<MROWS, 256>>>(p_h, ln_w + l*DM, ln_b + l*DM, p_ln);

        // (#4, profiled) xz = ln @ W_in^T — bf16x3 tensor GEMM
        mma_bf16x3<0><<<dim3(MB128, (2*DI)/128), 256>>>(
            p_ln, Wi, p_xz, MROWS, 2*DI, DM, DM, DM);

        // depthwise causal conv + silu (also zero-inits xdbl rows)
        conv_silu_kernel<<<MROWS, 256>>>(cw, cb);

        // x_dbl = xc @ W_x^T  (1184 x 80, K=1536) — split-K=4 atomic
        sgemm_small<64,16,16,4,1><<<dim3(MB64, XDBLN/16, 4), 256>>>(
            p_xc, Wx, p_xdbl, MROWS, XDBLN, DI, DI, DI/4);

        // selective scan with fused dt projection + D skip + gate
        scan_kernel<<<(BATCH*DI)/8, 128>>>(Al, Dl, Wd, db);

        // h += y @ W_out^T — bf16x3 split-K=4 (240 CTAs: one full wave), atomicAdd
        mma_bf16x3<1><<<dim3(MB128, DM/128, 4), 256>>>(
            p_y, Wo, p_h, MROWS, DM, DI, DI, DI/4);
    }

    // final layernorm straight into the output buffer
    ln_kernel<<<MROWS, 256>>>(p_h, lnf_w, lnf_b, out_h);
}

// round 13
// speedup vs baseline: 1.1138x; 1.1138x over previous
#include <cuda_runtime.h>
#include <cuda_bf16.h>
#include <math.h>
#include <stdint.h>

#define BATCH 8
#define NPATCH 196
#define LEN_KEEP 147
#define SEQL 148
#define DM 768
#define DI 1536
#define DSTATE 16
#define DTR 48
#define XDBLN 80
#define NLAYERS 12
#define MROWS (BATCH*SEQL)   // 1184

// ---------------- scratch buffers (device globals; no allocation) ----------------
__device__ float g_patches[MROWS*DM];
__device__ int   g_rowpatch[MROWS];
__device__ float g_h[MROWS*DM];
__device__ float g_ln[MROWS*DM];
__device__ float g_xz[MROWS*2*DI];
__device__ float g_xc[MROWS*DI];
__device__ float g_xdbl[MROWS*XDBLN];
__device__ float g_dt[MROWS*DI];
__device__ float g_y[MROWS*DI];

// ================= low-level helpers =================
__device__ __forceinline__ uint32_t smem_u32(const void* p) {
    uint32_t a;
    asm("{ .reg .u64 t; cvta.to.shared.u64 t, %1; cvt.u32.u64 %0, t; }" : "=r"(a) : "l"(p));
    return a;
}
__device__ __forceinline__ void ldsm4(uint32_t* r, uint32_t addr) {
    asm volatile("ldmatrix.sync.aligned.m8n8.x4.shared.b16 {%0,%1,%2,%3}, [%4];"
                 : "=r"(r[0]), "=r"(r[1]), "=r"(r[2]), "=r"(r[3]) : "r"(addr));
}
__device__ __forceinline__ void mma16816(float* d, const uint32_t* a, const uint32_t* b) {
    asm volatile("mma.sync.aligned.m16n8k16.row.col.f32.bf16.bf16.f32 "
                 "{%0,%1,%2,%3}, {%4,%5,%6,%7}, {%8,%9}, {%0,%1,%2,%3};"
                 : "+f"(d[0]), "+f"(d[1]), "+f"(d[2]), "+f"(d[3])
                 : "r"(a[0]), "r"(a[1]), "r"(a[2]), "r"(a[3]), "r"(b[0]), "r"(b[1]));
}

// ======== bf16x3 tensor GEMM: C[M,N] (+)= A[M,lda] * W[N,ldb]^T over K-slice ======
// 128x128 CTA tile, 8 warps (2x4), 64x32 warp tile, 16-float K stages (hi|lo bf16).
// EPI: 0 = plain store, 1 = atomicAdd accumulate (for split-K residual add)
template<int EPI>
__global__ __launch_bounds__(256, 2)
void mma_bf16x3(const float* __restrict__ A, const float* __restrict__ W,
                float* __restrict__ C, int M, int N, int lda, int ldb, int Klen) {
    constexpr int PITCH = 40;                 // bf16 elems per row: [hi 16 | lo 16 | pad 8]
    constexpr int ROWB  = PITCH * 2;          // 80 bytes
    constexpr int STAGEB = 128 * ROWB;        // bytes per stage buffer
    __shared__ __align__(16) __nv_bfloat16 As[2][128][PITCH];
    __shared__ __align__(16) __nv_bfloat16 Bs[2][128][PITCH];

    const int tid  = threadIdx.x;
    const int lane = tid & 31;
    const int wid  = tid >> 5;
    const int wm   = wid & 1;                 // 2 warps along M
    const int wn   = wid >> 1;                // 4 warps along N
    const int m0   = blockIdx.x * 128;
    const int n0   = blockIdx.y * 128;
    const int koff = blockIdx.z * Klen;

    float acc[4][4][4];
    #pragma unroll
    for (int i = 0; i < 4; i++)
        #pragma unroll
        for (int j = 0; j < 4; j++)
            #pragma unroll
            for (int q = 0; q < 4; q++) acc[i][j][q] = 0.0f;

    // conflict-free staging mapping
    const int lrow = (tid & 7) | (((tid >> 4) & 1) << 3) | ((tid >> 5) << 4);
    const int lkc  = ((tid >> 3) & 1) * 8;    // k-chunk: floats 0-7 or 8-15
    const int gmA  = m0 + lrow;
    const bool mok = (gmA < M);
    const float* aPtr = A + (size_t)gmA * lda + koff + lkc;
    const float* bPtr = W + (size_t)(n0 + lrow) * ldb + koff + lkc;

    const uint32_t aAddr = smem_u32(&As[0][wm*64 + (lane & 15)][0]) + ((lane >> 4) * 16);
    const uint32_t bAddr = smem_u32(&Bs[0][wn*32 + ((lane >> 4) << 3) + (lane & 7)][0])
                         + (((lane >> 3) & 1) * 16);

    const int KT = Klen / 16;

    // split-store: 8 floats -> hi bf16 16B chunk + lo bf16 16B chunk
    auto split_sts = [&](__nv_bfloat16 (*S)[PITCH], float4 v0, float4 v1) {
        float f[8] = {v0.x, v0.y, v0.z, v0.w, v1.x, v1.y, v1.z, v1.w};
        uint4 hi4, lo4;
        uint32_t* hp = (uint32_t*)&hi4;
        uint32_t* lp = (uint32_t*)&lo4;
        #pragma unroll
        for (int q = 0; q < 4; q++) {
            float x = f[2*q], y = f[2*q+1];
            __nv_bfloat162 h2 = __floats2bfloat162_rn(x, y);
            float2 hf = __bfloat1622float2(h2);
            __nv_bfloat162 l2 = __floats2bfloat162_rn(x - hf.x, y - hf.y);
            hp[q] = *(uint32_t*)&h2;
            lp[q] = *(uint32_t*)&l2;
        }
        *(uint4*)&S[lrow][lkc]      = hi4;
        *(uint4*)&S[lrow][16 + lkc] = lo4;
    };

    // ---- stage 0 ----
    {
        float4 va0 = make_float4(0,0,0,0), va1 = va0;
        if (mok) { va0 = *(const float4*)aPtr; va1 = *(const float4*)(aPtr + 4); }
        float4 vb0 = *(const float4*)bPtr, vb1 = *(const float4*)(bPtr + 4);
        split_sts(As[0], va0, va1);
        split_sts(Bs[0], vb0, vb1);
    }
    __syncthreads();

    int s = 0;
    for (int kt = 0; kt < KT; kt++) {
        float4 va0, va1, vb0, vb1;
        if (kt + 1 < KT) {
            int k0 = (kt + 1) * 16;
            va0 = make_float4(0,0,0,0); va1 = va0;
            if (mok) { va0 = *(const float4*)(aPtr + k0); va1 = *(const float4*)(aPtr + k0 + 4); }
            vb0 = *(const float4*)(bPtr + k0); vb1 = *(const float4*)(bPtr + k0 + 4);
        }

        // ---- compute stage s: acc += Ah*Bh + Ah*Bl + Al*Bh ----
        {
            const uint32_t aS = aAddr + s * STAGEB;
            const uint32_t bS = bAddr + s * STAGEB;
            uint32_t Af[4][4], Bh[4][2], Bl[4][2], t[4];

            #pragma unroll
            for (int mf = 0; mf < 4; mf++) ldsm4(Af[mf], aS + mf * 16 * ROWB);     // A hi
            ldsm4(t, bS);                 Bh[0][0]=t[0]; Bh[0][1]=t[1]; Bh[1][0]=t[2]; Bh[1][1]=t[3];
            ldsm4(t, bS + 16 * ROWB);     Bh[2][0]=t[0]; Bh[2][1]=t[1]; Bh[3][0]=t[2]; Bh[3][1]=t[3];
            #pragma unroll
            for (int mf = 0; mf < 4; mf++)
                #pragma unroll
                for (int nf = 0; nf < 4; nf++) mma16816(acc[mf][nf], Af[mf], Bh[nf]);

            ldsm4(t, bS + 32);            Bl[0][0]=t[0]; Bl[0][1]=t[1]; Bl[1][0]=t[2]; Bl[1][1]=t[3];
            ldsm4(t, bS + 16*ROWB + 32);  Bl[2][0]=t[0]; Bl[2][1]=t[1]; Bl[3][0]=t[2]; Bl[3][1]=t[3];
            #pragma unroll
            for (int mf = 0; mf < 4; mf++)
                #pragma unroll
                for (int nf = 0; nf < 4; nf++) mma16816(acc[mf][nf], Af[mf], Bl[nf]);

            #pragma unroll
            for (int mf = 0; mf < 4; mf++) ldsm4(Af[mf], aS + mf * 16 * ROWB + 32); // A lo
            #pragma unroll
            for (int mf = 0; mf < 4; mf++)
                #pragma unroll
                for (int nf = 0; nf < 4; nf++) mma16816(acc[mf][nf], Af[mf], Bh[nf]);
        }

        if (kt + 1 < KT) {
            int sn = s ^ 1;
            split_sts(As[sn], va0, va1);
            split_sts(Bs[sn], vb0, vb1);
            __syncthreads();
            s = sn;
        }
    }

    // ---- epilogue ----
    #pragma unroll
    for (int mf = 0; mf < 4; mf++) {
        int r0 = m0 + wm*64 + mf*16 + (lane >> 2);
        #pragma unroll
        for (int nf = 0; nf < 4; nf++) {
            int c = n0 + wn*32 + nf*8 + (lane & 3)*2;
            if (EPI == 0) {
                if (r0 < M)     *(float2*)&C[(size_t)r0 * N + c]     = make_float2(acc[mf][nf][0], acc[mf][nf][1]);
                if (r0 + 8 < M) *(float2*)&C[(size_t)(r0+8) * N + c] = make_float2(acc[mf][nf][2], acc[mf][nf][3]);
            } else {
                if (r0 < M) {
                    atomicAdd(&C[(size_t)r0 * N + c],     acc[mf][nf][0]);
                    atomicAdd(&C[(size_t)r0 * N + c + 1], acc[mf][nf][1]);
                }
                if (r0 + 8 < M) {
                    atomicAdd(&C[(size_t)(r0+8) * N + c],     acc[mf][nf][2]);
                    atomicAdd(&C[(size_t)(r0+8) * N + c + 1], acc[mf][nf][3]);
                }
            }
        }
    }
}

// ---------------- packed f32x2 helpers (FFMA2 kernels) ----------------------------
__device__ __forceinline__ void ffma2(unsigned long long& acc,
                                      unsigned long long a, unsigned long long b) {
    asm("fma.rn.f32x2 %0, %1, %2, %0;" : "+l"(acc) : "l"(a), "l"(b));
}
__device__ __forceinline__ unsigned long long pack2(float x, float y) {
    unsigned long long r;
    asm("mov.b64 %0, {%1, %2};" : "=l"(r) : "f"(x), "f"(y));
    return r;
}
__device__ __forceinline__ float2 unpack2(unsigned long long v) {
    float2 f;
    asm("mov.b64 {%0, %1}, %2;" : "=f"(f.x), "=f"(f.y) : "l"(v));
    return f;
}

// -------- fused masking + gather: every block recomputes ranks from noise --------
__global__ void maskgather_kernel(const float* __restrict__ noise,
                                  const float* __restrict__ pix,
                                  float* __restrict__ out_mask,
                                  float* __restrict__ out_ids) {
    __shared__ float s[NPATCH];
    __shared__ int p_sel;
    int m = blockIdx.x;
    int t = m % SEQL, b = m / SEQL;
    int tid = threadIdx.x;
    if (tid < NPATCH) s[tid] = noise[b*NPATCH + tid];
    __syncthreads();
    int rank = -1;
    if (tid < NPATCH) {
        float v = s[tid];
        rank = 0;
        #pragma unroll 4
        for (int j = 0; j < NPATCH; j++) {
            float u = s[j];
            rank += (u < v) || (u == v && j < tid);
        }
    }
    if (t == 0) {
        if (tid < NPATCH) {
            out_mask[b*NPATCH + tid] = (rank >= LEN_KEEP) ? 1.0f : 0.0f;
            out_ids [b*NPATCH + tid] = (float)rank;
        }
        if (tid == 0) g_rowpatch[m] = -1;
        for (int k = tid; k < DM; k += blockDim.x) g_patches[m*DM + k] = 0.0f;
        return;
    }
    if (rank == t - 1) p_sel = tid;      // exactly one thread matches
    __syncthreads();
    int p = p_sel;
    if (tid == 0) g_rowpatch[m] = p;
    int pi = p / 14, pj = p % 14;
    for (int k = tid; k < DM; k += blockDim.x) {
        int c = k >> 8, rem = k & 255, r = rem >> 4, cc = rem & 15;
        g_patches[m*DM + k] =
            pix[((size_t)(b*3 + c)*224 + pi*16 + r)*224 + pj*16 + cc];
    }
}

// =============== FFMA2 SGEMM (patch-embed and dt) =================================
// EPI: 1 patch-embed | 2 softplus(+dt_bias)
template<int EPI>
__global__ __launch_bounds__(256)
void sgemm3(const float* __restrict__ A, const float* __restrict__ W,
            float* __restrict__ C, int M, int N, int K, int lda, int Klen,
            const float* __restrict__ ep0, const float* __restrict__ ep1,
            const float* __restrict__ ep2, const int* __restrict__ rowinfo) {
    constexpr int BM = 64, BN = 64, BK = 16;
    constexpr int PA = 132;
    constexpr int PB = 68;
    __shared__ __align__(16) float As2[2][BK][PA];
    __shared__ __align__(16) float Bs [2][BK][PB];
    const int tid = threadIdx.x;
    const int m0 = blockIdx.x * BM;
    const int n0 = blockIdx.y * BN;
    const int koff = blockIdx.z * Klen;
    const int tx = tid & 15;
    const int ty = tid >> 4;
    unsigned long long acc[4][2];
    #pragma unroll
    for (int i = 0; i < 4; i++) { acc[i][0] = 0ull; acc[i][1] = 0ull; }
    const int KT = Klen / BK;
    const int li = tid >> 4, lj = tid & 15;
    #pragma unroll
    for (int r = 0; r < 4; r++) {
        int i = li + r*16;
        int gm = m0 + i;
        float va = (gm < M) ? A[(size_t)gm * lda + koff + lj] : 0.0f;
        *(unsigned long long*)&As2[0][lj][2*i] = pack2(va, va);
        Bs[0][lj][i] = W[(size_t)(n0 + i) * K + koff + lj];
    }
    __syncthreads();
    int s = 0;
    for (int kt = 0; kt < KT; kt++) {
        float ra[4], rb[4];
        if (kt + 1 < KT) {
            int k0 = koff + (kt + 1) * BK;
            #pragma unroll
            for (int r = 0; r < 4; r++) {
                int i = li + r*16;
                int gm = m0 + i;
                ra[r] = (gm < M) ? A[(size_t)gm * lda + k0 + lj] : 0.0f;
                rb[r] = W[(size_t)(n0 + i) * K + k0 + lj];
            }
        }
        #pragma unroll
        for (int kk = 0; kk < BK; kk++) {
            ulonglong2 a01 = *(const ulonglong2*)&As2[s][kk][ty*8];
            ulonglong2 a23 = *(const ulonglong2*)&As2[s][kk][ty*8 + 4];
            ulonglong2 bq  = *(const ulonglong2*)&Bs [s][kk][tx*4];
            ffma2(acc[0][0], a01.x, bq.x); ffma2(acc[0][1], a01.x, bq.y);
            ffma2(acc[1][0], a01.y, bq.x); ffma2(acc[1][1], a01.y, bq.y);
            ffma2(acc[2][0], a23.x, bq.x); ffma2(acc[2][1], a23.x, bq.y);
            ffma2(acc[3][0], a23.y, bq.x); ffma2(acc[3][1], a23.y, bq.y);
        }
        if (kt + 1 < KT) {
            int sn = s ^ 1;
            #pragma unroll
            for (int r = 0; r < 4; r++) {
                int i = li + r*16;
                *(unsigned long long*)&As2[sn][lj][2*i] = pack2(ra[r], ra[r]);
                Bs[sn][lj][i] = rb[r];
            }
            __syncthreads();
            s = sn;
        }
    }
    #pragma unroll
    for (int i = 0; i < 4; i++) {
        int m = m0 + ty*4 + i;
        if (m >= M) continue;
        int rp = 0;
        if (EPI == 1) rp = rowinfo[m];
        #pragma unroll
        for (int j = 0; j < 2; j++) {
            float2 v2 = unpack2(acc[i][j]);
            int n = n0 + tx*4 + j*2;
            if (EPI == 2) {
                float x0 = v2.x + ep0[n],   x1 = v2.y + ep0[n+1];
                v2.x = (x0 > 20.0f) ? x0 : log1pf(__expf(x0));
                v2.y = (x1 > 20.0f) ? x1 : log1pf(__expf(x1));
                *(float2*)&C[(size_t)m * N + n] = v2;
            } else { // EPI == 1
                float vv[2] = {v2.x, v2.y};
                #pragma unroll
                for (int q = 0; q < 2; q++) {
                    int nn = n + q;
                    float v = vv[q];
                    if (rp < 0) v = ep1[nn] + ep2[nn];
                    else        v = v + ep0[nn] + ep2[(size_t)(1+rp)*DM + nn];
                    C[(size_t)m * N + nn] = v;
                }
            }
        }
    }
}

// ---------------- small SGEMM for x_dbl (N=80), split-K with atomicAdd ------------
// Thread tile (2,2): 4 LDS per 4 FMA in the inner loop.
template<int BM, int BN, int BK, int TM, int TN>
__global__ __launch_bounds__(256)
void sgemm_small(const float* __restrict__ A, const float* __restrict__ W,
                 float* __restrict__ C, int M, int N, int K, int lda, int Klen) {
    __shared__ float As[BK][BM + 4];
    __shared__ float Bs[BK][BN + 4];
    const int tid = threadIdx.x;
    const int m0 = blockIdx.x * BM;
    const int n0 = blockIdx.y * BN;
    const int koff = blockIdx.z * Klen;
    constexpr int CT = BN / TN;
    const int tx = tid % CT;
    const int ty = tid / CT;
    float acc[TM][TN];
    #pragma unroll
    for (int i = 0; i < TM; i++)
        #pragma unroll
        for (int j = 0; j < TN; j++) acc[i][j] = 0.0f;
    constexpr int AREP = (BM * BK) / 256;
    constexpr int BREP = (BN * BK + 255) / 256;
    for (int k0 = koff; k0 < koff + Klen; k0 += BK) {
        #pragma unroll
        for (int r = 0; r < AREP; r++) {
            int idx = tid + r * 256;
            int i = idx / BK, j = idx % BK;
            int gm = m0 + i;
            As[j][i] = (gm < M) ? A[(size_t)gm * lda + k0 + j] : 0.0f;
        }
        #pragma unroll
        for (int r = 0; r < BREP; r++) {
            int idx = tid + r * 256;
            if (idx < BN * BK) {
                int i = idx / BK, j = idx % BK;
                Bs[j][i] = W[(size_t)(n0 + i) * K + k0 + j];
            }
        }
        __syncthreads();
        #pragma unroll
        for (int kk = 0; kk < BK; kk++) {
            float a[TM], bb[TN];
            #pragma unroll
            for (int i = 0; i < TM; i++) a[i] = As[kk][ty*TM + i];
            #pragma unroll
            for (int j = 0; j < TN; j++) bb[j] = Bs[kk][tx*TN + j];
            #pragma unroll
            for (int i = 0; i < TM; i++)
                #pragma unroll
                for (int j = 0; j < TN; j++)
                    acc[i][j] = fmaf(a[i], bb[j], acc[i][j]);
        }
        __syncthreads();
    }
    #pragma unroll
    for (int i = 0; i < TM; i++) {
        int m = m0 + ty*TM + i;
        if (m >= M) continue;
        #pragma unroll
        for (int j = 0; j < TN; j++) {
            int n = n0 + tx*TN + j;
            atomicAdd(&C[(size_t)m * N + n], acc[i][j]);
        }
    }
}

// ------- depthwise causal conv1d (k=4) + SiLU, float2 vectorized; zeroes xdbl ----
__global__ void conv_silu_kernel(const float* __restrict__ cw,
                                 const float* __restrict__ cb) {
    int m = blockIdx.x;
    int t = m % SEQL, b = m / SEQL;
    if (threadIdx.x < XDBLN) g_xdbl[(size_t)m*XDBLN + threadIdx.x] = 0.0f;
    for (int d2 = threadIdx.x; d2 < DI/2; d2 += blockDim.x) {
        int d = d2 * 2;
        float4 wA = *(const float4*)&cw[d*4];        // channel d weights
        float4 wB = *(const float4*)&cw[d*4 + 4];    // channel d+1 weights
        float2 s = *(const float2*)&cb[d];
        const float* base = g_xz + (size_t)(b*SEQL) * (2*DI) + d;
        if (t >= 3) { float2 v = *(const float2*)&base[(size_t)(t-3)*(2*DI)];
                      s.x = fmaf(wA.x, v.x, s.x); s.y = fmaf(wB.x, v.y, s.y); }
        if (t >= 2) { float2 v = *(const float2*)&base[(size_t)(t-2)*(2*DI)];
                      s.x = fmaf(wA.y, v.x, s.x); s.y = fmaf(wB.y, v.y, s.y); }
        if (t >= 1) { float2 v = *(const float2*)&base[(size_t)(t-1)*(2*DI)];
                      s.x = fmaf(wA.z, v.x, s.x); s.y = fmaf(wB.z, v.y, s.y); }
        { float2 v = *(const float2*)&base[(size_t)t*(2*DI)];
          s.x = fmaf(wA.w, v.x, s.x); s.y = fmaf(wB.w, v.y, s.y); }
        float2 o;
        o.x = s.x / (1.0f + __expf(-s.x));
        o.y = s.y / (1.0f + __expf(-s.y));
        *(float2*)&g_xc[(size_t)m*DI + d] = o;
    }
}

// ---------------- layernorm (row per block, 256 threads, DM=768) -----------------
__device__ __forceinline__ float block_reduce_sum_256(float v, float* sh, float* bc) {
    #pragma unroll
    for (int o = 16; o > 0; o >>= 1) v += __shfl_xor_sync(0xffffffffu, v, o);
    int w = threadIdx.x >> 5;
    if ((threadIdx.x & 31) == 0) sh[w] = v;
    __syncthreads();
    if (threadIdx.x == 0) {
        float s = 0.0f;
        #pragma unroll
        for (int i = 0; i < 8; i++) s += sh[i];
        *bc = s;
    }
    __syncthreads();
    return *bc;
}

__global__ void ln_kernel(const float* __restrict__ x, const float* __restrict__ w,
                          const float* __restrict__ bias, float* __restrict__ out) {
    __shared__ float sh[8];
    __shared__ float bc;
    int m = blockIdx.x, tid = threadIdx.x;
    const float* xr = x + (size_t)m * DM;
    float v0 = xr[tid], v1 = xr[tid + 256], v2 = xr[tid + 512];
    float mean = block_reduce_sum_256(v0 + v1 + v2, sh, &bc) * (1.0f / DM);
    float d0 = v0 - mean, d1 = v1 - mean, d2 = v2 - mean;
    __syncthreads();
    float var = block_reduce_sum_256(d0*d0 + d1*d1 + d2*d2, sh, &bc) * (1.0f / DM);
    float inv = rsqrtf(var + 1e-12f);
    float* o = out + (size_t)m * DM;
    o[tid]       = d0 * inv * w[tid]       + bias[tid];
    o[tid + 256] = d1 * inv * w[tid + 256] + bias[tid + 256];
    o[tid + 512] = d2 * inv * w[tid + 512] + bias[tid + 512];
}

// ---------------- selective scan: 16 lanes/channel, prefetched loads --------------
__global__ void scan_kernel(const float* __restrict__ A_log_l,
                            const float* __restrict__ Dp_l) {
    int lane = threadIdx.x & 31;
    int warp = threadIdx.x >> 5;
    int widx = blockIdx.x * 8 + warp;
    int ch = widx * 2 + (lane >> 4);       // 2 channels per warp
    int b = ch / DI, d = ch % DI;
    int n = lane & 15;
    float Av = -__expf(A_log_l[d*DSTATE + n]);
    float Dv = Dp_l[d];
    float h = 0.0f;
    int base = b * SEQL;
    // prefetch t=0
    float dt = g_dt[(size_t)base*DI + d];
    float xc = g_xc[(size_t)base*DI + d];
    float Bn = g_xdbl[(size_t)base*XDBLN + DTR + n];
    float Cn = g_xdbl[(size_t)base*XDBLN + DTR + DSTATE + n];
    for (int t = 0; t < SEQL; t++) {
        float dtN, xcN, BnN, CnN;
        if (t + 1 < SEQL) {
            int m1 = base + t + 1;
            dtN = g_dt[(size_t)m1*DI + d];
            xcN = g_xc[(size_t)m1*DI + d];
            BnN = g_xdbl[(size_t)m1*XDBLN + DTR + n];
            CnN = g_xdbl[(size_t)m1*XDBLN + DTR + DSTATE + n];
        }
        float dA = __expf(dt * Av);
        h = fmaf(dA, h, (dt * xc) * Bn);
        float p = h * Cn;
        p += __shfl_xor_sync(0xffffffffu, p, 8);
        p += __shfl_xor_sync(0xffffffffu, p, 4);
        p += __shfl_xor_sync(0xffffffffu, p, 2);
        p += __shfl_xor_sync(0xffffffffu, p, 1);
        if (n == 0) {
            int m = base + t;
            float z = g_xz[(size_t)m*(2*DI) + DI + d];
            float y = (p + xc * Dv) * (z / (1.0f + __expf(-z)));
            g_y[(size_t)m*DI + d] = y;
        }
        dt = dtN; xc = xcN; Bn = BnN; Cn = CnN;
    }
}

// ---------------- host launcher ---------------------------------------------------
extern "C" void kernel_launch(void* const* d_in, const int* in_sizes, int n_in,
                              void* d_out, int out_size) {
    const float* pixel     = (const float*)d_in[0];
    const float* noise     = (const float*)d_in[1];
    const float* conv_w    = (const float*)d_in[2];
    const float* conv_b    = (const float*)d_in[3];
    const float* cls_token = (const float*)d_in[4];
    const float* pos_embed = (const float*)d_in[5];
    const float* ln_w      = (const float*)d_in[6];
    const float* ln_b      = (const float*)d_in[7];
    const float* W_in      = (const float*)d_in[8];
    const float* conv1d_w  = (const float*)d_in[9];
    const float* conv1d_b  = (const float*)d_in[10];
    const float* W_x       = (const float*)d_in[11];
    const float* W_dt      = (const float*)d_in[12];
    const float* dt_bias   = (const float*)d_in[13];
    const float* A_log     = (const float*)d_in[14];
    const float* Dp        = (const float*)d_in[15];
    const float* W_out     = (const float*)d_in[16];
    const float* lnf_w     = (const float*)d_in[17];
    const float* lnf_b     = (const float*)d_in[18];

    float* out      = (float*)d_out;
    float* out_h    = out;                       // (8,148,768)
    float* out_mask = out + (size_t)MROWS*DM;    // (8,196)
    float* out_ids  = out_mask + BATCH*NPATCH;   // (8,196) as float

    float *p_patches, *p_h, *p_ln, *p_xz, *p_xc, *p_xdbl, *p_dt, *p_y;
    int *p_rowpatch;
    cudaGetSymbolAddress((void**)&p_patches, g_patches);
    cudaGetSymbolAddress((void**)&p_h,       g_h);
    cudaGetSymbolAddress((void**)&p_ln,      g_ln);
    cudaGetSymbolAddress((void**)&p_xz,      g_xz);
    cudaGetSymbolAddress((void**)&p_xc,      g_xc);
    cudaGetSymbolAddress((void**)&p_xdbl,    g_xdbl);
    cudaGetSymbolAddress((void**)&p_dt,      g_dt);
    cudaGetSymbolAddress((void**)&p_y,       g_y);
    cudaGetSymbolAddress((void**)&p_rowpatch, g_rowpatch);

    const int MB64  = (MROWS + 63) / 64;     // 19
    const int MB128 = (MROWS + 127) / 128;   // 10

    // fused masking + patch gather (launch #1), then patch-embed GEMM (#2)
    maskgather_kernel<<<MROWS, 256>>>(noise, pixel, out_mask, out_ids);
    sgemm3<1><<<dim3(MB64, DM/64, 1), 256>>>(p_patches, conv_w, p_h,
        MROWS, DM, DM, DM, DM, conv_b, cls_token, pos_embed, p_rowpatch);

    for (int l = 0; l < NLAYERS; l++) {
        const float* Wi  = W_in     + (size_t)l * (2*DI) * DM;
        const float* cw  = conv1d_w + (size_t)l * DI * 4;
        const float* cb  = conv1d_b + (size_t)l * DI;
        const float* Wx  = W_x      + (size_t)l * XDBLN * DI;
        const float* Wd  = W_dt     + (size_t)l * DI * DTR;
        const float* db  = dt_bias  + (size_t)l * DI;
        const float* Al  = A_log    + (size_t)l * DI * DSTATE;
        const float* Dl  = Dp       + (size_t)l * DI;
        const float* Wo  = W_out    + (size_t)l * DM * DI;

        // layernorm (#3 in layer 0)
        ln_kernel<<<MROWS, 256>>>(p_h, ln_w + l*DM, ln_b + l*DM, p_ln);

        // (#4, profiled) xz = ln @ W_in^T — bf16x3 tensor GEMM
        mma_bf16x3<0><<<dim3(MB128, (2*DI)/128), 256>>>(
            p_ln, Wi, p_xz, MROWS, 2*DI, DM, DM, DM);

        // depthwise causal conv + silu (also zero-inits xdbl rows)
        conv_silu_kernel<<<MROWS, 256>>>(cw, cb);

        // x_dbl = xc @ W_x^T  (1184 x 80, K=1536) — split-K=4 atomic
        sgemm_small<64,16,16,2,2><<<dim3(MB64, XDBLN/16, 4), 256>>>(
            p_xc, Wx, p_xdbl, MROWS, XDBLN, DI, DI, DI/4);

        // dt = softplus(x_dbl[:, :48] @ W_dt^T + dt_bias)
        sgemm3<2><<<dim3(MB64, DI/64, 1), 256>>>(p_xdbl, Wd, p_dt,
            MROWS, DI, DTR, XDBLN, DTR, db, nullptr, nullptr, nullptr);

        // selective scan + D skip + gate
        scan_kernel<<<(BATCH*DI)/16, 256>>>(Al, Dl);

        // h += y @ W_out^T — bf16x3 split-K=4 (240 CTAs: one full wave), atomicAdd
        mma_bf16x3<1><<<dim3(MB128, DM/128, 4), 256>>>(
            p_y, Wo, p_h, MROWS, DM, DI, DI, DI/4);
    }

    // final layernorm straight into the output buffer
    ln_kernel<<<MROWS, 256>>>(p_h, lnf_w, lnf_b, out_h);
}